// round 14
// baseline (speedup 1.0000x reference)
#include <cuda_runtime.h>
#include <cuda_bf16.h>
#include <cstdint>

#define NN 50000
#define EE 800000
#define DD 128

typedef unsigned long long ull_t;

// ---------------- scratch (__device__ globals; no runtime allocation) ------
__device__ float g_q[NN * DD];
__device__ float g_k[NN * DD];
__device__ float g_v[NN * DD];
__device__ ull_t g_xh[NN * 32];    // X split hi: [NN][128] bf16 row-major
__device__ ull_t g_xl[NN * 32];    // X split lo
__device__ ull_t g_hh[NN * 32];    // h (agg out) split hi
__device__ ull_t g_hl[NN * 32];    // h split lo
__device__ ull_t g_wth[4 * 4096];  // W^T hi: [mat][128 n][128 k] bf16
__device__ ull_t g_wtl[4 * 4096];  // W^T lo
__device__ int   g_cnt[NN];        // zero-initialized; scatter restores zeros
__device__ int   g_off[NN + 1];
__device__ int   g_csrc[EE];
__device__ int   g_part[64];
__device__ int   g_pofs[64];
__device__ int   g_stride;         // 1 = int32 indices, 2 = int64 (low word)

// ---------------- bf16 helpers ---------------------------------------------
__device__ __forceinline__ void split4(float4 v, ull_t& hp, ull_t& lp)
{
    __nv_bfloat16 h0 = __float2bfloat16(v.x);
    __nv_bfloat16 h1 = __float2bfloat16(v.y);
    __nv_bfloat16 h2 = __float2bfloat16(v.z);
    __nv_bfloat16 h3 = __float2bfloat16(v.w);
    __nv_bfloat16 l0 = __float2bfloat16(v.x - __bfloat162float(h0));
    __nv_bfloat16 l1 = __float2bfloat16(v.y - __bfloat162float(h1));
    __nv_bfloat16 l2 = __float2bfloat16(v.z - __bfloat162float(h2));
    __nv_bfloat16 l3 = __float2bfloat16(v.w - __bfloat162float(h3));
    hp = (ull_t)__bfloat16_as_ushort(h0)
       | ((ull_t)__bfloat16_as_ushort(h1) << 16)
       | ((ull_t)__bfloat16_as_ushort(h2) << 32)
       | ((ull_t)__bfloat16_as_ushort(h3) << 48);
    lp = (ull_t)__bfloat16_as_ushort(l0)
       | ((ull_t)__bfloat16_as_ushort(l1) << 16)
       | ((ull_t)__bfloat16_as_ushort(l2) << 32)
       | ((ull_t)__bfloat16_as_ushort(l3) << 48);
}

// ---------------- warp-level mma.sync (sm_80+ feature; legal on sm_103) ----
__device__ __forceinline__ void mma_bf16(float* c, const uint32_t* a,
                                         const uint32_t* b)
{
    asm volatile(
        "mma.sync.aligned.m16n8k16.row.col.f32.bf16.bf16.f32 "
        "{%0,%1,%2,%3}, {%4,%5,%6,%7}, {%8,%9}, {%0,%1,%2,%3};"
        : "+f"(c[0]), "+f"(c[1]), "+f"(c[2]), "+f"(c[3])
        : "r"(a[0]), "r"(a[1]), "r"(a[2]), "r"(a[3]), "r"(b[0]), "r"(b[1]));
}

#define SROW 136   // smem Wt row pitch in bf16 (272B = 68 words == 4 mod 32)

// ---------------- MMA GEMM core: 128x128 tile, 8 warps ---------------------
__device__ __forceinline__ void mma_core(const unsigned short* __restrict__ Ah,
                                         const unsigned short* __restrict__ Al,
                                         const ull_t* __restrict__ Wh,
                                         const ull_t* __restrict__ Wl,
                                         const float* __restrict__ bias,
                                         float* __restrict__ C)
{
    extern __shared__ char smem[];
    unsigned short* sh = (unsigned short*)smem;   // Wt hi [128][SROW]
    unsigned short* sl = sh + 128 * SROW;         // Wt lo

    const int tid  = threadIdx.x;
    const int lane = tid & 31;
    const int w    = tid >> 5;
    const int row0 = blockIdx.x * 128;

    for (int i = tid; i < 4096; i += 256) {
        int r = i >> 5, c = i & 31;
        *(ull_t*)(sh + r * SROW + c * 4) = Wh[i];
        *(ull_t*)(sl + r * SROW + c * 4) = Wl[i];
    }
    __syncthreads();

    const int wr0 = (w & 3) * 32;
    const int wc0 = (w >> 2) * 64;
    const int qr  = lane >> 2;
    const int qm  = lane & 3;

    float acc[2][8][4];
#pragma unroll
    for (int mt = 0; mt < 2; mt++)
#pragma unroll
        for (int nt = 0; nt < 8; nt++)
#pragma unroll
            for (int j = 0; j < 4; j++) acc[mt][nt][j] = 0.f;

#pragma unroll
    for (int c8 = 0; c8 < 8; c8++) {
        const int k0 = c8 * 16;
        uint32_t ah[2][4], al[2][4];
#pragma unroll
        for (int mt = 0; mt < 2; mt++) {
            int r1 = row0 + wr0 + mt * 16 + qr;
            int r2 = r1 + 8;
            bool p1 = r1 < NN, p2 = r2 < NN;
            const unsigned short* a1p = Ah + (size_t)r1 * 128 + k0 + qm * 2;
            const unsigned short* a2p = Ah + (size_t)r2 * 128 + k0 + qm * 2;
            const unsigned short* b1p = Al + (size_t)r1 * 128 + k0 + qm * 2;
            const unsigned short* b2p = Al + (size_t)r2 * 128 + k0 + qm * 2;
            ah[mt][0] = p1 ? *(const uint32_t*)(a1p)     : 0u;
            ah[mt][1] = p2 ? *(const uint32_t*)(a2p)     : 0u;
            ah[mt][2] = p1 ? *(const uint32_t*)(a1p + 8) : 0u;
            ah[mt][3] = p2 ? *(const uint32_t*)(a2p + 8) : 0u;
            al[mt][0] = p1 ? *(const uint32_t*)(b1p)     : 0u;
            al[mt][1] = p2 ? *(const uint32_t*)(b2p)     : 0u;
            al[mt][2] = p1 ? *(const uint32_t*)(b1p + 8) : 0u;
            al[mt][3] = p2 ? *(const uint32_t*)(b2p + 8) : 0u;
        }
#pragma unroll
        for (int nt = 0; nt < 8; nt++) {
            const int nrow = wc0 + nt * 8 + qr;
            uint32_t bh[2], bl[2];
            const unsigned short* ph = sh + nrow * SROW + k0 + qm * 2;
            const unsigned short* pl = sl + nrow * SROW + k0 + qm * 2;
            bh[0] = *(const uint32_t*)(ph);
            bh[1] = *(const uint32_t*)(ph + 8);
            bl[0] = *(const uint32_t*)(pl);
            bl[1] = *(const uint32_t*)(pl + 8);
#pragma unroll
            for (int mt = 0; mt < 2; mt++) {
                mma_bf16(acc[mt][nt], ah[mt], bh);
                mma_bf16(acc[mt][nt], ah[mt], bl);
                mma_bf16(acc[mt][nt], al[mt], bh);
            }
        }
    }

    // epilogue
#pragma unroll
    for (int nt = 0; nt < 8; nt++) {
        const int cc = wc0 + nt * 8 + qm * 2;
        const float2 bb = *(const float2*)&bias[cc];
#pragma unroll
        for (int mt = 0; mt < 2; mt++) {
            int r1 = row0 + wr0 + mt * 16 + qr;
            int r2 = r1 + 8;
            if (r1 < NN) {
                float2 o = make_float2(acc[mt][nt][0] + bb.x,
                                       acc[mt][nt][1] + bb.y);
                *(float2*)&C[(size_t)r1 * DD + cc] = o;
            }
            if (r2 < NN) {
                float2 o = make_float2(acc[mt][nt][2] + bb.x,
                                       acc[mt][nt][3] + bb.y);
                *(float2*)&C[(size_t)r2 * DD + cc] = o;
            }
        }
    }
}

#define MMA_SMEM (2 * 128 * SROW * 2)   // 69632 bytes

__global__ __launch_bounds__(256, 2)
void mma_qkv_kernel(const float* __restrict__ bq, const float* __restrict__ bk,
                    const float* __restrict__ bv)
{
    int sel = blockIdx.y;
    const float* bias = (sel == 0) ? bq : (sel == 1) ? bk : bv;
    float* C          = (sel == 0) ? g_q : (sel == 1) ? g_k : g_v;
    mma_core((const unsigned short*)g_xh, (const unsigned short*)g_xl,
             g_wth + sel * 4096, g_wtl + sel * 4096, bias, C);
}

__global__ __launch_bounds__(256, 2)
void mma_out_kernel(const float* __restrict__ bo, float* __restrict__ out)
{
    mma_core((const unsigned short*)g_hh, (const unsigned short*)g_hl,
             g_wth + 3 * 4096, g_wtl + 3 * 4096, bo, out);
}

// ---------------- prep kernels ---------------------------------------------
__global__ void prep_x_kernel(const float* __restrict__ x)
{
    int i = blockIdx.x * blockDim.x + threadIdx.x;   // NN*32 ull slots
    if (i < NN * 32) {
        float4 v = *(const float4*)&x[i * 4];
        ull_t hp, lp;
        split4(v, hp, lp);
        g_xh[i] = hp;
        g_xl[i] = lp;
    }
}

__global__ void prep_w_kernel(const float* __restrict__ Wq,
                              const float* __restrict__ Wk,
                              const float* __restrict__ Wv,
                              const float* __restrict__ Wo)
{
    int id = blockIdx.x * blockDim.x + threadIdx.x;
    if (id >= 4 * 4096) return;
    int mat = id >> 12;
    int n   = (id >> 5) & 127;
    int kc  = id & 31;
    const float* W = (mat == 0) ? Wq : (mat == 1) ? Wk : (mat == 2) ? Wv : Wo;
    float4 v = make_float4(W[(kc * 4 + 0) * DD + n], W[(kc * 4 + 1) * DD + n],
                           W[(kc * 4 + 2) * DD + n], W[(kc * 4 + 3) * DD + n]);
    ull_t hp, lp;
    split4(v, hp, lp);
    g_wth[id] = hp;
    g_wtl[id] = lp;
}

// ---------------- dtype sniffer -------------------------------------------
__global__ void sniff_kernel(const int* __restrict__ dstw)
{
    __shared__ int any_nonzero;
    if (threadIdx.x == 0) any_nonzero = 0;
    __syncthreads();
    int v = dstw[2 * threadIdx.x + 1];
    if (v != 0) atomicOr(&any_nonzero, 1);
    __syncthreads();
    if (threadIdx.x == 0) g_stride = any_nonzero ? 1 : 2;
}

// ---------------- CSR build ------------------------------------------------
__global__ void zero_cnt_kernel()
{
    int i = blockIdx.x * blockDim.x + threadIdx.x;
    if (i < NN) g_cnt[i] = 0;
}

__global__ void hist_kernel(const int* __restrict__ dstw)
{
    int e = blockIdx.x * blockDim.x + threadIdx.x;
    if (e < EE) {
        int d = dstw[e * g_stride];
        atomicAdd(&g_cnt[d], 1);
    }
}

#define SCAN_NB 49

__global__ void scan_part_kernel()
{
    __shared__ int warpsum[8];
    int base = blockIdx.x * 1024 + threadIdx.x * 4;
    int s = 0;
#pragma unroll
    for (int j = 0; j < 4; j++) {
        int i = base + j;
        if (i < NN) s += g_cnt[i];
    }
    for (int o = 16; o > 0; o >>= 1) s += __shfl_down_sync(0xffffffffu, s, o);
    if ((threadIdx.x & 31) == 0) warpsum[threadIdx.x >> 5] = s;
    __syncthreads();
    if (threadIdx.x < 8) {
        int v = warpsum[threadIdx.x];
        for (int o = 4; o > 0; o >>= 1) v += __shfl_down_sync(0xffu, v, o);
        if (threadIdx.x == 0) g_part[blockIdx.x] = v;
    }
}

__global__ void scan_mid_kernel()
{
    __shared__ int sh[64];
    int t = threadIdx.x;
    int v = (t < SCAN_NB) ? g_part[t] : 0;
    sh[t] = v;
    __syncthreads();
    for (int o = 1; o < 64; o <<= 1) {
        int u = (t >= o) ? sh[t - o] : 0;
        __syncthreads();
        sh[t] += u;
        __syncthreads();
    }
    if (t < SCAN_NB) g_pofs[t] = (t == 0) ? 0 : sh[t - 1];
}

__global__ void scan_final_kernel()
{
    __shared__ int wpref[8];
    int t = threadIdx.x, lane = t & 31, w = t >> 5;
    int base = blockIdx.x * 1024 + t * 4;
    int c[4];
    int s = 0;
#pragma unroll
    for (int j = 0; j < 4; j++) {
        int i = base + j;
        c[j] = (i < NN) ? g_cnt[i] : 0;
        s += c[j];
    }
    int inc = s;
    for (int o = 1; o < 32; o <<= 1) {
        int u = __shfl_up_sync(0xffffffffu, inc, o);
        if (lane >= o) inc += u;
    }
    if (lane == 31) wpref[w] = inc;
    __syncthreads();
    if (t < 8) {
        int v = wpref[t];
        for (int o = 1; o < 8; o <<= 1) {
            int u = __shfl_up_sync(0xffu, v, o);
            if (t >= o) v += u;
        }
        wpref[t] = v;
    }
    __syncthreads();
    int run = inc - s + (w ? wpref[w - 1] : 0) + g_pofs[blockIdx.x];
#pragma unroll
    for (int j = 0; j < 4; j++) {
        int i = base + j;
        run += c[j];
        if (i < NN) g_off[i + 1] = run;
    }
    if (blockIdx.x == 0 && t == 0) g_off[0] = 0;
}

__global__ void scatter_kernel(const int* __restrict__ srcw,
                               const int* __restrict__ dstw)
{
    int e = blockIdx.x * blockDim.x + threadIdx.x;
    if (e < EE) {
        int st  = g_stride;
        int d   = dstw[e * st];
        int s   = srcw[e * st];
        int pos = atomicSub(&g_cnt[d], 1);
        g_csrc[g_off[d] + pos - 1] = s;
    }
}

// ---------------- aggregation: warp per node, 8-way edge unroll ------------
__global__ void agg_kernel()
{
    int w    = (blockIdx.x * blockDim.x + threadIdx.x) >> 5;
    int lane = threadIdx.x & 31;
    if (w >= NN) return;

    const float4 q4 = *(const float4*)&g_q[w * DD + lane * 4];
    const float qx = q4.x * 0.25f;
    const float qy = q4.y * 0.25f;
    const float qz = q4.z * 0.25f;
    const float qw = q4.w * 0.25f;

    float zx = 0.f, zy = 0.f, zz = 0.f, zw = 0.f;
    float ax = 0.f, ay = 0.f, az = 0.f, aw = 0.f;

    const int beg = g_off[w];
    const int end = g_off[w + 1];

    for (int j0 = beg; j0 < end; j0 += 32) {
        int myS = (j0 + lane < end) ? g_csrc[j0 + lane] : 0;
        int cnt = min(32, end - j0);
        int t = 0;
        for (; t + 8 <= cnt; t += 8) {
            float4 kk[8], vv[8];
#pragma unroll
            for (int u = 0; u < 8; u++) {
                int s = __shfl_sync(0xffffffffu, myS, t + u);
                kk[u] = *(const float4*)&g_k[(size_t)s * DD + lane * 4];
                vv[u] = *(const float4*)&g_v[(size_t)s * DD + lane * 4];
            }
#pragma unroll
            for (int u = 0; u < 8; u++) {
                float m;
                m = __expf(kk[u].x * qx); zx += m; ax += m * vv[u].x;
                m = __expf(kk[u].y * qy); zy += m; ay += m * vv[u].y;
                m = __expf(kk[u].z * qz); zz += m; az += m * vv[u].z;
                m = __expf(kk[u].w * qw); zw += m; aw += m * vv[u].w;
            }
        }
        for (; t + 4 <= cnt; t += 4) {
            float4 kk[4], vv[4];
#pragma unroll
            for (int u = 0; u < 4; u++) {
                int s = __shfl_sync(0xffffffffu, myS, t + u);
                kk[u] = *(const float4*)&g_k[(size_t)s * DD + lane * 4];
                vv[u] = *(const float4*)&g_v[(size_t)s * DD + lane * 4];
            }
#pragma unroll
            for (int u = 0; u < 4; u++) {
                float m;
                m = __expf(kk[u].x * qx); zx += m; ax += m * vv[u].x;
                m = __expf(kk[u].y * qy); zy += m; ay += m * vv[u].y;
                m = __expf(kk[u].z * qz); zz += m; az += m * vv[u].z;
                m = __expf(kk[u].w * qw); zw += m; aw += m * vv[u].w;
            }
        }
        for (; t < cnt; t++) {
            int s = __shfl_sync(0xffffffffu, myS, t);
            const float4 kk = *(const float4*)&g_k[(size_t)s * DD + lane * 4];
            const float4 vv = *(const float4*)&g_v[(size_t)s * DD + lane * 4];
            float m;
            m = __expf(kk.x * qx); zx += m; ax += m * vv.x;
            m = __expf(kk.y * qy); zy += m; ay += m * vv.y;
            m = __expf(kk.z * qz); zz += m; az += m * vv.z;
            m = __expf(kk.w * qw); zw += m; aw += m * vv.w;
        }
    }

    float4 o = make_float4(ax / zx, ay / zy, az / zz, aw / zw);
    ull_t hp, lp;
    split4(o, hp, lp);
    g_hh[w * 32 + lane] = hp;
    g_hl[w * 32 + lane] = lp;
}

// ---------------- launch ---------------------------------------------------
extern "C" void kernel_launch(void* const* d_in, const int* in_sizes, int n_in,
                              void* d_out, int out_size)
{
    const float* x   = (const float*)d_in[0];
    const int*   src = (const int*)d_in[1];
    const int*   dst = (const int*)d_in[2];
    const float* Wq  = (const float*)d_in[3];
    const float* bq  = (const float*)d_in[4];
    const float* Wk  = (const float*)d_in[5];
    const float* bk  = (const float*)d_in[6];
    const float* Wv  = (const float*)d_in[7];
    const float* bv  = (const float*)d_in[8];
    const float* Wo  = (const float*)d_in[9];
    const float* bo  = (const float*)d_in[10];
    float*       out = (float*)d_out;

    cudaFuncSetAttribute(mma_qkv_kernel,
                         cudaFuncAttributeMaxDynamicSharedMemorySize, MMA_SMEM);
    cudaFuncSetAttribute(mma_out_kernel,
                         cudaFuncAttributeMaxDynamicSharedMemorySize, MMA_SMEM);

    const int mma_blocks  = (NN + 127) / 128;      // 391
    const int zero_blocks = (NN + 255) / 256;      // 196
    const int edge_blocks = (EE + 255) / 256;      // 3125
    const int agg_blocks  = (NN * 32 + 255) / 256; // 6250
    const int px_blocks   = (NN * 32 + 255) / 256; // 6250
    const int pw_blocks   = (4 * 4096 + 255) / 256;

    // bf16 splits first so mma_qkv sits at launch index 3 (profiled slot)
    prep_x_kernel<<<px_blocks, 256>>>(x);
    prep_w_kernel<<<pw_blocks, 256>>>(Wq, Wk, Wv, Wo);
    sniff_kernel<<<1, 512>>>(dst);
    mma_qkv_kernel<<<dim3(mma_blocks, 3), 256, MMA_SMEM>>>(bq, bk, bv);

    // CSR by dst
    zero_cnt_kernel<<<zero_blocks, 256>>>();
    hist_kernel<<<edge_blocks, 256>>>(dst);
    scan_part_kernel<<<SCAN_NB, 256>>>();
    scan_mid_kernel<<<1, 64>>>();
    scan_final_kernel<<<SCAN_NB, 256>>>();
    scatter_kernel<<<edge_blocks, 256>>>(src, dst);

    // edge softmax-aggregate (fp32 gathers, 8-way unroll)
    agg_kernel<<<agg_blocks, 256>>>();

    // output projection
    mma_out_kernel<<<mma_blocks, 256, MMA_SMEM>>>(bo, out);
}

// round 15
// speedup vs baseline: 1.1589x; 1.1589x over previous
#include <cuda_runtime.h>
#include <cuda_bf16.h>
#include <cstdint>

#define NN 50000
#define EE 800000
#define DD 128

typedef unsigned long long ull_t;

// ---------------- scratch (__device__ globals; no runtime allocation) ------
__device__ float g_q[NN * DD];
__device__ float g_k[NN * DD];
__device__ float g_v[NN * DD];
__device__ ull_t g_xh[NN * 32];    // X split hi: [NN][32] ull (128 bf16/row)
__device__ ull_t g_xl[NN * 32];    // X split lo
__device__ ull_t g_hh[NN * 32];    // h (agg out) split hi
__device__ ull_t g_hl[NN * 32];    // h split lo
__device__ ull_t g_wth[4 * 4096];  // W^T hi: [mat][128 n][128 k] bf16
__device__ ull_t g_wtl[4 * 4096];  // W^T lo
__device__ int   g_cnt[NN];        // zero-initialized; scatter restores zeros
__device__ int   g_off[NN + 1];
__device__ int   g_csrc[EE];
__device__ int   g_part[64];
__device__ int   g_pofs[64];
__device__ int   g_stride;         // 1 = int32 indices, 2 = int64 (low word)

// ---------------- bf16 helpers ---------------------------------------------
__device__ __forceinline__ void split4(float4 v, ull_t& hp, ull_t& lp)
{
    __nv_bfloat16 h0 = __float2bfloat16(v.x);
    __nv_bfloat16 h1 = __float2bfloat16(v.y);
    __nv_bfloat16 h2 = __float2bfloat16(v.z);
    __nv_bfloat16 h3 = __float2bfloat16(v.w);
    __nv_bfloat16 l0 = __float2bfloat16(v.x - __bfloat162float(h0));
    __nv_bfloat16 l1 = __float2bfloat16(v.y - __bfloat162float(h1));
    __nv_bfloat16 l2 = __float2bfloat16(v.z - __bfloat162float(h2));
    __nv_bfloat16 l3 = __float2bfloat16(v.w - __bfloat162float(h3));
    hp = (ull_t)__bfloat16_as_ushort(h0)
       | ((ull_t)__bfloat16_as_ushort(h1) << 16)
       | ((ull_t)__bfloat16_as_ushort(h2) << 32)
       | ((ull_t)__bfloat16_as_ushort(h3) << 48);
    lp = (ull_t)__bfloat16_as_ushort(l0)
       | ((ull_t)__bfloat16_as_ushort(l1) << 16)
       | ((ull_t)__bfloat16_as_ushort(l2) << 32)
       | ((ull_t)__bfloat16_as_ushort(l3) << 48);
}

// ---------------- warp-level mma.sync (sm_80+ feature; legal on sm_103) ----
__device__ __forceinline__ void mma_bf16(float* c, const uint32_t* a,
                                         const uint32_t* b)
{
    asm volatile(
        "mma.sync.aligned.m16n8k16.row.col.f32.bf16.bf16.f32 "
        "{%0,%1,%2,%3}, {%4,%5,%6,%7}, {%8,%9}, {%0,%1,%2,%3};"
        : "+f"(c[0]), "+f"(c[1]), "+f"(c[2]), "+f"(c[3])
        : "r"(a[0]), "r"(a[1]), "r"(a[2]), "r"(a[3]), "r"(b[0]), "r"(b[1]));
}

#define SROW 136     // smem Wt row pitch in bf16 (272B)
#define APITCH 5     // smem A chunk row pitch in ull (40B: 32B data + 8B pad)

// ---------------- MMA GEMM core: 128x128 tile, 8 warps ---------------------
// A chunks staged via smem (coalesced ull global loads, LDS fragment reads).
__device__ __forceinline__ void mma_core(const ull_t* __restrict__ Ah,
                                         const ull_t* __restrict__ Al,
                                         const ull_t* __restrict__ Wh,
                                         const ull_t* __restrict__ Wl,
                                         const float* __restrict__ bias,
                                         float* __restrict__ C)
{
    extern __shared__ char smem[];
    unsigned short* sh = (unsigned short*)smem;         // Wt hi [128][SROW]
    unsigned short* sl = sh + 128 * SROW;               // Wt lo
    ull_t* sa_h = (ull_t*)(sl + 128 * SROW);            // A hi [128][APITCH]
    ull_t* sa_l = sa_h + 128 * APITCH;                  // A lo

    const int tid  = threadIdx.x;
    const int lane = tid & 31;
    const int w    = tid >> 5;
    const int row0 = blockIdx.x * 128;

    for (int i = tid; i < 4096; i += 256) {
        int r = i >> 5, c = i & 31;
        *(ull_t*)(sh + r * SROW + c * 4) = Wh[i];
        *(ull_t*)(sl + r * SROW + c * 4) = Wl[i];
    }

    const int wr0 = (w & 3) * 32;
    const int wc0 = (w >> 2) * 64;
    const int qr  = lane >> 2;
    const int qm  = lane & 3;

    float acc[2][8][4];
#pragma unroll
    for (int mt = 0; mt < 2; mt++)
#pragma unroll
        for (int nt = 0; nt < 8; nt++)
#pragma unroll
            for (int j = 0; j < 4; j++) acc[mt][nt][j] = 0.f;

#pragma unroll
    for (int c8 = 0; c8 < 8; c8++) {
        const int k0 = c8 * 16;
        __syncthreads();   // prior-iter reads (and W staging) complete
        // stage A chunk: 128 rows x 4 ull x 2 splits; coalesced
#pragma unroll
        for (int it = 0; it < 2; it++) {
            int i  = tid + it * 256;      // 0..511
            int r  = i >> 2;
            int wz = i & 3;
            int gr = row0 + r;
            ull_t vh = 0, vl = 0;
            if (gr < NN) {
                vh = Ah[(size_t)gr * 32 + c8 * 4 + wz];
                vl = Al[(size_t)gr * 32 + c8 * 4 + wz];
            }
            sa_h[r * APITCH + wz] = vh;
            sa_l[r * APITCH + wz] = vl;
        }
        __syncthreads();

        uint32_t ah[2][4], al[2][4];
#pragma unroll
        for (int mt = 0; mt < 2; mt++) {
            int rl1 = wr0 + mt * 16 + qr;
            int rl2 = rl1 + 8;
            const uint32_t* h1 = (const uint32_t*)(sa_h + rl1 * APITCH);
            const uint32_t* h2 = (const uint32_t*)(sa_h + rl2 * APITCH);
            const uint32_t* l1 = (const uint32_t*)(sa_l + rl1 * APITCH);
            const uint32_t* l2 = (const uint32_t*)(sa_l + rl2 * APITCH);
            ah[mt][0] = h1[qm];
            ah[mt][1] = h2[qm];
            ah[mt][2] = h1[qm + 4];
            ah[mt][3] = h2[qm + 4];
            al[mt][0] = l1[qm];
            al[mt][1] = l2[qm];
            al[mt][2] = l1[qm + 4];
            al[mt][3] = l2[qm + 4];
        }
#pragma unroll
        for (int nt = 0; nt < 8; nt++) {
            const int nrow = wc0 + nt * 8 + qr;
            uint32_t bh[2], bl[2];
            const unsigned short* ph = sh + nrow * SROW + k0 + qm * 2;
            const unsigned short* pl = sl + nrow * SROW + k0 + qm * 2;
            bh[0] = *(const uint32_t*)(ph);
            bh[1] = *(const uint32_t*)(ph + 8);
            bl[0] = *(const uint32_t*)(pl);
            bl[1] = *(const uint32_t*)(pl + 8);
#pragma unroll
            for (int mt = 0; mt < 2; mt++) {
                mma_bf16(acc[mt][nt], ah[mt], bh);
                mma_bf16(acc[mt][nt], ah[mt], bl);
                mma_bf16(acc[mt][nt], al[mt], bh);
            }
        }
    }

    // epilogue
#pragma unroll
    for (int nt = 0; nt < 8; nt++) {
        const int cc = wc0 + nt * 8 + qm * 2;
        const float2 bb = *(const float2*)&bias[cc];
#pragma unroll
        for (int mt = 0; mt < 2; mt++) {
            int r1 = row0 + wr0 + mt * 16 + qr;
            int r2 = r1 + 8;
            if (r1 < NN) {
                float2 o = make_float2(acc[mt][nt][0] + bb.x,
                                       acc[mt][nt][1] + bb.y);
                *(float2*)&C[(size_t)r1 * DD + cc] = o;
            }
            if (r2 < NN) {
                float2 o = make_float2(acc[mt][nt][2] + bb.x,
                                       acc[mt][nt][3] + bb.y);
                *(float2*)&C[(size_t)r2 * DD + cc] = o;
            }
        }
    }
}

#define MMA_SMEM (2 * 128 * SROW * 2 + 2 * 128 * APITCH * 8)  // 79872 bytes

__global__ __launch_bounds__(256, 2)
void mma_qkv_kernel(const float* __restrict__ bq, const float* __restrict__ bk,
                    const float* __restrict__ bv)
{
    int sel = blockIdx.y;
    const float* bias = (sel == 0) ? bq : (sel == 1) ? bk : bv;
    float* C          = (sel == 0) ? g_q : (sel == 1) ? g_k : g_v;
    mma_core(g_xh, g_xl, g_wth + sel * 4096, g_wtl + sel * 4096, bias, C);
}

__global__ __launch_bounds__(256, 2)
void mma_out_kernel(const float* __restrict__ bo, float* __restrict__ out)
{
    mma_core(g_hh, g_hl, g_wth + 3 * 4096, g_wtl + 3 * 4096, bo, out);
}

// ---------------- prep kernels ---------------------------------------------
__global__ void prep_x_kernel(const float* __restrict__ x)
{
    int i = blockIdx.x * blockDim.x + threadIdx.x;   // NN*32 ull slots
    if (i < NN * 32) {
        float4 v = *(const float4*)&x[i * 4];
        ull_t hp, lp;
        split4(v, hp, lp);
        g_xh[i] = hp;
        g_xl[i] = lp;
    }
}

__global__ void prep_w_kernel(const float* __restrict__ Wq,
                              const float* __restrict__ Wk,
                              const float* __restrict__ Wv,
                              const float* __restrict__ Wo)
{
    int id = blockIdx.x * blockDim.x + threadIdx.x;
    if (id >= 4 * 4096) return;
    int mat = id >> 12;
    int n   = (id >> 5) & 127;
    int kc  = id & 31;
    const float* W = (mat == 0) ? Wq : (mat == 1) ? Wk : (mat == 2) ? Wv : Wo;
    float4 v = make_float4(W[(kc * 4 + 0) * DD + n], W[(kc * 4 + 1) * DD + n],
                           W[(kc * 4 + 2) * DD + n], W[(kc * 4 + 3) * DD + n]);
    ull_t hp, lp;
    split4(v, hp, lp);
    g_wth[id] = hp;
    g_wtl[id] = lp;
}

// ---------------- dtype sniffer -------------------------------------------
__global__ void sniff_kernel(const int* __restrict__ dstw)
{
    __shared__ int any_nonzero;
    if (threadIdx.x == 0) any_nonzero = 0;
    __syncthreads();
    int v = dstw[2 * threadIdx.x + 1];
    if (v != 0) atomicOr(&any_nonzero, 1);
    __syncthreads();
    if (threadIdx.x == 0) g_stride = any_nonzero ? 1 : 2;
}

// ---------------- CSR build ------------------------------------------------
__global__ void zero_cnt_kernel()
{
    int i = blockIdx.x * blockDim.x + threadIdx.x;
    if (i < NN) g_cnt[i] = 0;
}

__global__ void hist_kernel(const int* __restrict__ dstw)
{
    int e = blockIdx.x * blockDim.x + threadIdx.x;
    if (e < EE) {
        int d = dstw[e * g_stride];
        atomicAdd(&g_cnt[d], 1);
    }
}

#define SCAN_NB 49

__global__ void scan_part_kernel()
{
    __shared__ int warpsum[8];
    int base = blockIdx.x * 1024 + threadIdx.x * 4;
    int s = 0;
#pragma unroll
    for (int j = 0; j < 4; j++) {
        int i = base + j;
        if (i < NN) s += g_cnt[i];
    }
    for (int o = 16; o > 0; o >>= 1) s += __shfl_down_sync(0xffffffffu, s, o);
    if ((threadIdx.x & 31) == 0) warpsum[threadIdx.x >> 5] = s;
    __syncthreads();
    if (threadIdx.x < 8) {
        int v = warpsum[threadIdx.x];
        for (int o = 4; o > 0; o >>= 1) v += __shfl_down_sync(0xffu, v, o);
        if (threadIdx.x == 0) g_part[blockIdx.x] = v;
    }
}

__global__ void scan_mid_kernel()
{
    __shared__ int sh[64];
    int t = threadIdx.x;
    int v = (t < SCAN_NB) ? g_part[t] : 0;
    sh[t] = v;
    __syncthreads();
    for (int o = 1; o < 64; o <<= 1) {
        int u = (t >= o) ? sh[t - o] : 0;
        __syncthreads();
        sh[t] += u;
        __syncthreads();
    }
    if (t < SCAN_NB) g_pofs[t] = (t == 0) ? 0 : sh[t - 1];
}

__global__ void scan_final_kernel()
{
    __shared__ int wpref[8];
    int t = threadIdx.x, lane = t & 31, w = t >> 5;
    int base = blockIdx.x * 1024 + t * 4;
    int c[4];
    int s = 0;
#pragma unroll
    for (int j = 0; j < 4; j++) {
        int i = base + j;
        c[j] = (i < NN) ? g_cnt[i] : 0;
        s += c[j];
    }
    int inc = s;
    for (int o = 1; o < 32; o <<= 1) {
        int u = __shfl_up_sync(0xffffffffu, inc, o);
        if (lane >= o) inc += u;
    }
    if (lane == 31) wpref[w] = inc;
    __syncthreads();
    if (t < 8) {
        int v = wpref[t];
        for (int o = 1; o < 8; o <<= 1) {
            int u = __shfl_up_sync(0xffu, v, o);
            if (t >= o) v += u;
        }
        wpref[t] = v;
    }
    __syncthreads();
    int run = inc - s + (w ? wpref[w - 1] : 0) + g_pofs[blockIdx.x];
#pragma unroll
    for (int j = 0; j < 4; j++) {
        int i = base + j;
        run += c[j];
        if (i < NN) g_off[i + 1] = run;
    }
    if (blockIdx.x == 0 && t == 0) g_off[0] = 0;
}

__global__ void scatter_kernel(const int* __restrict__ srcw,
                               const int* __restrict__ dstw)
{
    int e = blockIdx.x * blockDim.x + threadIdx.x;
    if (e < EE) {
        int st  = g_stride;
        int d   = dstw[e * st];
        int s   = srcw[e * st];
        int pos = atomicSub(&g_cnt[d], 1);
        g_csrc[g_off[d] + pos - 1] = s;
    }
}

// ---------------- aggregation: warp per node, 4-way edge unroll (R13) ------
__global__ void agg_kernel()
{
    int w    = (blockIdx.x * blockDim.x + threadIdx.x) >> 5;
    int lane = threadIdx.x & 31;
    if (w >= NN) return;

    const float4 q4 = *(const float4*)&g_q[w * DD + lane * 4];
    const float qx = q4.x * 0.25f;
    const float qy = q4.y * 0.25f;
    const float qz = q4.z * 0.25f;
    const float qw = q4.w * 0.25f;

    float zx = 0.f, zy = 0.f, zz = 0.f, zw = 0.f;
    float ax = 0.f, ay = 0.f, az = 0.f, aw = 0.f;

    const int beg = g_off[w];
    const int end = g_off[w + 1];

    for (int j0 = beg; j0 < end; j0 += 32) {
        int myS = (j0 + lane < end) ? g_csrc[j0 + lane] : 0;
        int cnt = min(32, end - j0);
        int t = 0;
        for (; t + 4 <= cnt; t += 4) {
            int s0 = __shfl_sync(0xffffffffu, myS, t);
            int s1 = __shfl_sync(0xffffffffu, myS, t + 1);
            int s2 = __shfl_sync(0xffffffffu, myS, t + 2);
            int s3 = __shfl_sync(0xffffffffu, myS, t + 3);
            float4 k0 = *(const float4*)&g_k[(size_t)s0 * DD + lane * 4];
            float4 k1 = *(const float4*)&g_k[(size_t)s1 * DD + lane * 4];
            float4 k2 = *(const float4*)&g_k[(size_t)s2 * DD + lane * 4];
            float4 k3 = *(const float4*)&g_k[(size_t)s3 * DD + lane * 4];
            float4 v0 = *(const float4*)&g_v[(size_t)s0 * DD + lane * 4];
            float4 v1 = *(const float4*)&g_v[(size_t)s1 * DD + lane * 4];
            float4 v2 = *(const float4*)&g_v[(size_t)s2 * DD + lane * 4];
            float4 v3 = *(const float4*)&g_v[(size_t)s3 * DD + lane * 4];
            float m;
            m = __expf(k0.x * qx); zx += m; ax += m * v0.x;
            m = __expf(k0.y * qy); zy += m; ay += m * v0.y;
            m = __expf(k0.z * qz); zz += m; az += m * v0.z;
            m = __expf(k0.w * qw); zw += m; aw += m * v0.w;
            m = __expf(k1.x * qx); zx += m; ax += m * v1.x;
            m = __expf(k1.y * qy); zy += m; ay += m * v1.y;
            m = __expf(k1.z * qz); zz += m; az += m * v1.z;
            m = __expf(k1.w * qw); zw += m; aw += m * v1.w;
            m = __expf(k2.x * qx); zx += m; ax += m * v2.x;
            m = __expf(k2.y * qy); zy += m; ay += m * v2.y;
            m = __expf(k2.z * qz); zz += m; az += m * v2.z;
            m = __expf(k2.w * qw); zw += m; aw += m * v2.w;
            m = __expf(k3.x * qx); zx += m; ax += m * v3.x;
            m = __expf(k3.y * qy); zy += m; ay += m * v3.y;
            m = __expf(k3.z * qz); zz += m; az += m * v3.z;
            m = __expf(k3.w * qw); zw += m; aw += m * v3.w;
        }
        for (; t < cnt; t++) {
            int s = __shfl_sync(0xffffffffu, myS, t);
            const float4 kk = *(const float4*)&g_k[(size_t)s * DD + lane * 4];
            const float4 vv = *(const float4*)&g_v[(size_t)s * DD + lane * 4];
            float m;
            m = __expf(kk.x * qx); zx += m; ax += m * vv.x;
            m = __expf(kk.y * qy); zy += m; ay += m * vv.y;
            m = __expf(kk.z * qz); zz += m; az += m * vv.z;
            m = __expf(kk.w * qw); zw += m; aw += m * vv.w;
        }
    }

    float4 o = make_float4(ax / zx, ay / zy, az / zz, aw / zw);
    ull_t hp, lp;
    split4(o, hp, lp);
    g_hh[w * 32 + lane] = hp;
    g_hl[w * 32 + lane] = lp;
}

// ---------------- launch ---------------------------------------------------
extern "C" void kernel_launch(void* const* d_in, const int* in_sizes, int n_in,
                              void* d_out, int out_size)
{
    const float* x   = (const float*)d_in[0];
    const int*   src = (const int*)d_in[1];
    const int*   dst = (const int*)d_in[2];
    const float* Wq  = (const float*)d_in[3];
    const float* bq  = (const float*)d_in[4];
    const float* Wk  = (const float*)d_in[5];
    const float* bk  = (const float*)d_in[6];
    const float* Wv  = (const float*)d_in[7];
    const float* bv  = (const float*)d_in[8];
    const float* Wo  = (const float*)d_in[9];
    const float* bo  = (const float*)d_in[10];
    float*       out = (float*)d_out;

    cudaFuncSetAttribute(mma_qkv_kernel,
                         cudaFuncAttributeMaxDynamicSharedMemorySize, MMA_SMEM);
    cudaFuncSetAttribute(mma_out_kernel,
                         cudaFuncAttributeMaxDynamicSharedMemorySize, MMA_SMEM);

    const int mma_blocks  = (NN + 127) / 128;      // 391
    const int zero_blocks = (NN + 255) / 256;      // 196
    const int edge_blocks = (EE + 255) / 256;      // 3125
    const int agg_blocks  = (NN * 32 + 255) / 256; // 6250
    const int px_blocks   = (NN * 32 + 255) / 256; // 6250
    const int pw_blocks   = (4 * 4096 + 255) / 256;

    // bf16 splits first so mma_qkv sits at launch index 3 (profiled slot)
    prep_x_kernel<<<px_blocks, 256>>>(x);
    prep_w_kernel<<<pw_blocks, 256>>>(Wq, Wk, Wv, Wo);
    sniff_kernel<<<1, 512>>>(dst);
    mma_qkv_kernel<<<dim3(mma_blocks, 3), 256, MMA_SMEM>>>(bq, bk, bv);

    // CSR by dst
    zero_cnt_kernel<<<zero_blocks, 256>>>();
    hist_kernel<<<edge_blocks, 256>>>(dst);
    scan_part_kernel<<<SCAN_NB, 256>>>();
    scan_mid_kernel<<<1, 64>>>();
    scan_final_kernel<<<SCAN_NB, 256>>>();
    scatter_kernel<<<edge_blocks, 256>>>(src, dst);

    // edge softmax-aggregate (fp32 gathers, 4-way unroll)
    agg_kernel<<<agg_blocks, 256>>>();

    // output projection
    mma_out_kernel<<<mma_blocks, 256, MMA_SMEM>>>(bo, out);
}

// round 16
// speedup vs baseline: 1.1713x; 1.0107x over previous
#include <cuda_runtime.h>
#include <cuda_bf16.h>
#include <cstdint>

#define NN 50000
#define EE 800000
#define DD 128

typedef unsigned long long ull_t;

// ---------------- scratch (__device__ globals; no runtime allocation) ------
__device__ float g_q[NN * DD];
__device__ float g_k[NN * DD];
__device__ float g_v[NN * DD];
__device__ ull_t g_xh[NN * 32];    // X split hi: [NN][32] ull (128 bf16/row)
__device__ ull_t g_xl[NN * 32];    // X split lo
__device__ ull_t g_hh[NN * 32];    // h (agg out) split hi
__device__ ull_t g_hl[NN * 32];    // h split lo
__device__ ull_t g_wth[4 * 4096];  // W^T hi: [mat][128 n][128 k] bf16
__device__ ull_t g_wtl[4 * 4096];  // W^T lo
__device__ int   g_cnt[NN];        // zero-initialized; scatter restores zeros
__device__ int   g_off[NN + 1];
__device__ int   g_csrc[EE];
__device__ int   g_part[64];
__device__ int   g_pofs[64];
__device__ int   g_stride;         // 1 = int32 indices, 2 = int64 (low word)

// ---------------- bf16 helpers ---------------------------------------------
__device__ __forceinline__ void split4(float4 v, ull_t& hp, ull_t& lp)
{
    __nv_bfloat16 h0 = __float2bfloat16(v.x);
    __nv_bfloat16 h1 = __float2bfloat16(v.y);
    __nv_bfloat16 h2 = __float2bfloat16(v.z);
    __nv_bfloat16 h3 = __float2bfloat16(v.w);
    __nv_bfloat16 l0 = __float2bfloat16(v.x - __bfloat162float(h0));
    __nv_bfloat16 l1 = __float2bfloat16(v.y - __bfloat162float(h1));
    __nv_bfloat16 l2 = __float2bfloat16(v.z - __bfloat162float(h2));
    __nv_bfloat16 l3 = __float2bfloat16(v.w - __bfloat162float(h3));
    hp = (ull_t)__bfloat16_as_ushort(h0)
       | ((ull_t)__bfloat16_as_ushort(h1) << 16)
       | ((ull_t)__bfloat16_as_ushort(h2) << 32)
       | ((ull_t)__bfloat16_as_ushort(h3) << 48);
    lp = (ull_t)__bfloat16_as_ushort(l0)
       | ((ull_t)__bfloat16_as_ushort(l1) << 16)
       | ((ull_t)__bfloat16_as_ushort(l2) << 32)
       | ((ull_t)__bfloat16_as_ushort(l3) << 48);
}

// ---------------- warp-level mma.sync (sm_80+ feature; legal on sm_103) ----
__device__ __forceinline__ void mma_bf16(float* c, const uint32_t* a,
                                         const uint32_t* b)
{
    asm volatile(
        "mma.sync.aligned.m16n8k16.row.col.f32.bf16.bf16.f32 "
        "{%0,%1,%2,%3}, {%4,%5,%6,%7}, {%8,%9}, {%0,%1,%2,%3};"
        : "+f"(c[0]), "+f"(c[1]), "+f"(c[2]), "+f"(c[3])
        : "r"(a[0]), "r"(a[1]), "r"(a[2]), "r"(a[3]), "r"(b[0]), "r"(b[1]));
}

#define SROW 136     // smem Wt row pitch in bf16 (272B)
#define APITCH 5     // smem A chunk row pitch in ull (40B: 32B data + 8B pad)

// ---------------- MMA GEMM core: 128x128 tile, 8 warps ---------------------
// A staged via smem; B frags hoisted per chunk; MMAs issued term-major so
// same-accumulator HMMAs are 15 instructions apart (no RAW stalls).
__device__ __forceinline__ void mma_core(const ull_t* __restrict__ Ah,
                                         const ull_t* __restrict__ Al,
                                         const ull_t* __restrict__ Wh,
                                         const ull_t* __restrict__ Wl,
                                         const float* __restrict__ bias,
                                         float* __restrict__ C)
{
    extern __shared__ char smem[];
    unsigned short* sh = (unsigned short*)smem;         // Wt hi [128][SROW]
    unsigned short* sl = sh + 128 * SROW;               // Wt lo
    ull_t* sa_h = (ull_t*)(sl + 128 * SROW);            // A hi [128][APITCH]
    ull_t* sa_l = sa_h + 128 * APITCH;                  // A lo

    const int tid  = threadIdx.x;
    const int lane = tid & 31;
    const int w    = tid >> 5;
    const int row0 = blockIdx.x * 128;

    for (int i = tid; i < 4096; i += 256) {
        int r = i >> 5, c = i & 31;
        *(ull_t*)(sh + r * SROW + c * 4) = Wh[i];
        *(ull_t*)(sl + r * SROW + c * 4) = Wl[i];
    }

    const int wr0 = (w & 3) * 32;
    const int wc0 = (w >> 2) * 64;
    const int qr  = lane >> 2;
    const int qm  = lane & 3;

    float acc[2][8][4];
#pragma unroll
    for (int mt = 0; mt < 2; mt++)
#pragma unroll
        for (int nt = 0; nt < 8; nt++)
#pragma unroll
            for (int j = 0; j < 4; j++) acc[mt][nt][j] = 0.f;

#pragma unroll
    for (int c8 = 0; c8 < 8; c8++) {
        const int k0 = c8 * 16;
        __syncthreads();   // prior-iter reads (and W staging) complete
        // stage A chunk: 128 rows x 4 ull x 2 splits; coalesced
#pragma unroll
        for (int it = 0; it < 2; it++) {
            int i  = tid + it * 256;      // 0..511
            int r  = i >> 2;
            int wz = i & 3;
            int gr = row0 + r;
            ull_t vh = 0, vl = 0;
            if (gr < NN) {
                vh = Ah[(size_t)gr * 32 + c8 * 4 + wz];
                vl = Al[(size_t)gr * 32 + c8 * 4 + wz];
            }
            sa_h[r * APITCH + wz] = vh;
            sa_l[r * APITCH + wz] = vl;
        }
        __syncthreads();

        // A fragments
        uint32_t ah[2][4], al[2][4];
#pragma unroll
        for (int mt = 0; mt < 2; mt++) {
            int rl1 = wr0 + mt * 16 + qr;
            int rl2 = rl1 + 8;
            const uint32_t* h1 = (const uint32_t*)(sa_h + rl1 * APITCH);
            const uint32_t* h2 = (const uint32_t*)(sa_h + rl2 * APITCH);
            const uint32_t* l1 = (const uint32_t*)(sa_l + rl1 * APITCH);
            const uint32_t* l2 = (const uint32_t*)(sa_l + rl2 * APITCH);
            ah[mt][0] = h1[qm];
            ah[mt][1] = h2[qm];
            ah[mt][2] = h1[qm + 4];
            ah[mt][3] = h2[qm + 4];
            al[mt][0] = l1[qm];
            al[mt][1] = l2[qm];
            al[mt][2] = l1[qm + 4];
            al[mt][3] = l2[qm + 4];
        }

        // B fragments for all 8 nt
        uint32_t bh[8][2], bl[8][2];
#pragma unroll
        for (int nt = 0; nt < 8; nt++) {
            const int nrow = wc0 + nt * 8 + qr;
            const unsigned short* ph = sh + nrow * SROW + k0 + qm * 2;
            const unsigned short* pl = sl + nrow * SROW + k0 + qm * 2;
            bh[nt][0] = *(const uint32_t*)(ph);
            bh[nt][1] = *(const uint32_t*)(ph + 8);
            bl[nt][0] = *(const uint32_t*)(pl);
            bl[nt][1] = *(const uint32_t*)(pl + 8);
        }

        // term-major MMA issue: 16 independent accs between same-acc MMAs
#pragma unroll
        for (int nt = 0; nt < 8; nt++)
#pragma unroll
            for (int mt = 0; mt < 2; mt++)
                mma_bf16(acc[mt][nt], ah[mt], bh[nt]);
#pragma unroll
        for (int nt = 0; nt < 8; nt++)
#pragma unroll
            for (int mt = 0; mt < 2; mt++)
                mma_bf16(acc[mt][nt], ah[mt], bl[nt]);
#pragma unroll
        for (int nt = 0; nt < 8; nt++)
#pragma unroll
            for (int mt = 0; mt < 2; mt++)
                mma_bf16(acc[mt][nt], al[mt], bh[nt]);
    }

    // epilogue
#pragma unroll
    for (int nt = 0; nt < 8; nt++) {
        const int cc = wc0 + nt * 8 + qm * 2;
        const float2 bb = *(const float2*)&bias[cc];
#pragma unroll
        for (int mt = 0; mt < 2; mt++) {
            int r1 = row0 + wr0 + mt * 16 + qr;
            int r2 = r1 + 8;
            if (r1 < NN) {
                float2 o = make_float2(acc[mt][nt][0] + bb.x,
                                       acc[mt][nt][1] + bb.y);
                *(float2*)&C[(size_t)r1 * DD + cc] = o;
            }
            if (r2 < NN) {
                float2 o = make_float2(acc[mt][nt][2] + bb.x,
                                       acc[mt][nt][3] + bb.y);
                *(float2*)&C[(size_t)r2 * DD + cc] = o;
            }
        }
    }
}

#define MMA_SMEM (2 * 128 * SROW * 2 + 2 * 128 * APITCH * 8)  // 79872 bytes

__global__ __launch_bounds__(256, 2)
void mma_qkv_kernel(const float* __restrict__ bq, const float* __restrict__ bk,
                    const float* __restrict__ bv)
{
    int sel = blockIdx.y;
    const float* bias = (sel == 0) ? bq : (sel == 1) ? bk : bv;
    float* C          = (sel == 0) ? g_q : (sel == 1) ? g_k : g_v;
    mma_core(g_xh, g_xl, g_wth + sel * 4096, g_wtl + sel * 4096, bias, C);
}

__global__ __launch_bounds__(256, 2)
void mma_out_kernel(const float* __restrict__ bo, float* __restrict__ out)
{
    mma_core(g_hh, g_hl, g_wth + 3 * 4096, g_wtl + 3 * 4096, bo, out);
}

// ---------------- prep kernels ---------------------------------------------
__global__ void prep_x_kernel(const float* __restrict__ x)
{
    int i = blockIdx.x * blockDim.x + threadIdx.x;   // NN*32 ull slots
    if (i < NN * 32) {
        float4 v = *(const float4*)&x[i * 4];
        ull_t hp, lp;
        split4(v, hp, lp);
        g_xh[i] = hp;
        g_xl[i] = lp;
    }
}

__global__ void prep_w_kernel(const float* __restrict__ Wq,
                              const float* __restrict__ Wk,
                              const float* __restrict__ Wv,
                              const float* __restrict__ Wo)
{
    int id = blockIdx.x * blockDim.x + threadIdx.x;
    if (id >= 4 * 4096) return;
    int mat = id >> 12;
    int n   = (id >> 5) & 127;
    int kc  = id & 31;
    const float* W = (mat == 0) ? Wq : (mat == 1) ? Wk : (mat == 2) ? Wv : Wo;
    float4 v = make_float4(W[(kc * 4 + 0) * DD + n], W[(kc * 4 + 1) * DD + n],
                           W[(kc * 4 + 2) * DD + n], W[(kc * 4 + 3) * DD + n]);
    ull_t hp, lp;
    split4(v, hp, lp);
    g_wth[id] = hp;
    g_wtl[id] = lp;
}

// ---------------- dtype sniffer -------------------------------------------
__global__ void sniff_kernel(const int* __restrict__ dstw)
{
    __shared__ int any_nonzero;
    if (threadIdx.x == 0) any_nonzero = 0;
    __syncthreads();
    int v = dstw[2 * threadIdx.x + 1];
    if (v != 0) atomicOr(&any_nonzero, 1);
    __syncthreads();
    if (threadIdx.x == 0) g_stride = any_nonzero ? 1 : 2;
}

// ---------------- CSR build ------------------------------------------------
__global__ void zero_cnt_kernel()
{
    int i = blockIdx.x * blockDim.x + threadIdx.x;
    if (i < NN) g_cnt[i] = 0;
}

__global__ void hist_kernel(const int* __restrict__ dstw)
{
    int e = blockIdx.x * blockDim.x + threadIdx.x;
    if (e < EE) {
        int d = dstw[e * g_stride];
        atomicAdd(&g_cnt[d], 1);
    }
}

#define SCAN_NB 49

__global__ void scan_part_kernel()
{
    __shared__ int warpsum[8];
    int base = blockIdx.x * 1024 + threadIdx.x * 4;
    int s = 0;
#pragma unroll
    for (int j = 0; j < 4; j++) {
        int i = base + j;
        if (i < NN) s += g_cnt[i];
    }
    for (int o = 16; o > 0; o >>= 1) s += __shfl_down_sync(0xffffffffu, s, o);
    if ((threadIdx.x & 31) == 0) warpsum[threadIdx.x >> 5] = s;
    __syncthreads();
    if (threadIdx.x < 8) {
        int v = warpsum[threadIdx.x];
        for (int o = 4; o > 0; o >>= 1) v += __shfl_down_sync(0xffu, v, o);
        if (threadIdx.x == 0) g_part[blockIdx.x] = v;
    }
}

__global__ void scan_mid_kernel()
{
    __shared__ int sh[64];
    int t = threadIdx.x;
    int v = (t < SCAN_NB) ? g_part[t] : 0;
    sh[t] = v;
    __syncthreads();
    for (int o = 1; o < 64; o <<= 1) {
        int u = (t >= o) ? sh[t - o] : 0;
        __syncthreads();
        sh[t] += u;
        __syncthreads();
    }
    if (t < SCAN_NB) g_pofs[t] = (t == 0) ? 0 : sh[t - 1];
}

__global__ void scan_final_kernel()
{
    __shared__ int wpref[8];
    int t = threadIdx.x, lane = t & 31, w = t >> 5;
    int base = blockIdx.x * 1024 + t * 4;
    int c[4];
    int s = 0;
#pragma unroll
    for (int j = 0; j < 4; j++) {
        int i = base + j;
        c[j] = (i < NN) ? g_cnt[i] : 0;
        s += c[j];
    }
    int inc = s;
    for (int o = 1; o < 32; o <<= 1) {
        int u = __shfl_up_sync(0xffffffffu, inc, o);
        if (lane >= o) inc += u;
    }
    if (lane == 31) wpref[w] = inc;
    __syncthreads();
    if (t < 8) {
        int v = wpref[t];
        for (int o = 1; o < 8; o <<= 1) {
            int u = __shfl_up_sync(0xffu, v, o);
            if (t >= o) v += u;
        }
        wpref[t] = v;
    }
    __syncthreads();
    int run = inc - s + (w ? wpref[w - 1] : 0) + g_pofs[blockIdx.x];
#pragma unroll
    for (int j = 0; j < 4; j++) {
        int i = base + j;
        run += c[j];
        if (i < NN) g_off[i + 1] = run;
    }
    if (blockIdx.x == 0 && t == 0) g_off[0] = 0;
}

__global__ void scatter_kernel(const int* __restrict__ srcw,
                               const int* __restrict__ dstw)
{
    int e = blockIdx.x * blockDim.x + threadIdx.x;
    if (e < EE) {
        int st  = g_stride;
        int d   = dstw[e * st];
        int s   = srcw[e * st];
        int pos = atomicSub(&g_cnt[d], 1);
        g_csrc[g_off[d] + pos - 1] = s;
    }
}

// ---------------- aggregation: warp per node, 4-way edge unroll (R13) ------
__global__ void agg_kernel()
{
    int w    = (blockIdx.x * blockDim.x + threadIdx.x) >> 5;
    int lane = threadIdx.x & 31;
    if (w >= NN) return;

    const float4 q4 = *(const float4*)&g_q[w * DD + lane * 4];
    const float qx = q4.x * 0.25f;
    const float qy = q4.y * 0.25f;
    const float qz = q4.z * 0.25f;
    const float qw = q4.w * 0.25f;

    float zx = 0.f, zy = 0.f, zz = 0.f, zw = 0.f;
    float ax = 0.f, ay = 0.f, az = 0.f, aw = 0.f;

    const int beg = g_off[w];
    const int end = g_off[w + 1];

    for (int j0 = beg; j0 < end; j0 += 32) {
        int myS = (j0 + lane < end) ? g_csrc[j0 + lane] : 0;
        int cnt = min(32, end - j0);
        int t = 0;
        for (; t + 4 <= cnt; t += 4) {
            int s0 = __shfl_sync(0xffffffffu, myS, t);
            int s1 = __shfl_sync(0xffffffffu, myS, t + 1);
            int s2 = __shfl_sync(0xffffffffu, myS, t + 2);
            int s3 = __shfl_sync(0xffffffffu, myS, t + 3);
            float4 k0 = *(const float4*)&g_k[(size_t)s0 * DD + lane * 4];
            float4 k1 = *(const float4*)&g_k[(size_t)s1 * DD + lane * 4];
            float4 k2 = *(const float4*)&g_k[(size_t)s2 * DD + lane * 4];
            float4 k3 = *(const float4*)&g_k[(size_t)s3 * DD + lane * 4];
            float4 v0 = *(const float4*)&g_v[(size_t)s0 * DD + lane * 4];
            float4 v1 = *(const float4*)&g_v[(size_t)s1 * DD + lane * 4];
            float4 v2 = *(const float4*)&g_v[(size_t)s2 * DD + lane * 4];
            float4 v3 = *(const float4*)&g_v[(size_t)s3 * DD + lane * 4];
            float m;
            m = __expf(k0.x * qx); zx += m; ax += m * v0.x;
            m = __expf(k0.y * qy); zy += m; ay += m * v0.y;
            m = __expf(k0.z * qz); zz += m; az += m * v0.z;
            m = __expf(k0.w * qw); zw += m; aw += m * v0.w;
            m = __expf(k1.x * qx); zx += m; ax += m * v1.x;
            m = __expf(k1.y * qy); zy += m; ay += m * v1.y;
            m = __expf(k1.z * qz); zz += m; az += m * v1.z;
            m = __expf(k1.w * qw); zw += m; aw += m * v1.w;
            m = __expf(k2.x * qx); zx += m; ax += m * v2.x;
            m = __expf(k2.y * qy); zy += m; ay += m * v2.y;
            m = __expf(k2.z * qz); zz += m; az += m * v2.z;
            m = __expf(k2.w * qw); zw += m; aw += m * v2.w;
            m = __expf(k3.x * qx); zx += m; ax += m * v3.x;
            m = __expf(k3.y * qy); zy += m; ay += m * v3.y;
            m = __expf(k3.z * qz); zz += m; az += m * v3.z;
            m = __expf(k3.w * qw); zw += m; aw += m * v3.w;
        }
        for (; t < cnt; t++) {
            int s = __shfl_sync(0xffffffffu, myS, t);
            const float4 kk = *(const float4*)&g_k[(size_t)s * DD + lane * 4];
            const float4 vv = *(const float4*)&g_v[(size_t)s * DD + lane * 4];
            float m;
            m = __expf(kk.x * qx); zx += m; ax += m * vv.x;
            m = __expf(kk.y * qy); zy += m; ay += m * vv.y;
            m = __expf(kk.z * qz); zz += m; az += m * vv.z;
            m = __expf(kk.w * qw); zw += m; aw += m * vv.w;
        }
    }

    float4 o = make_float4(ax / zx, ay / zy, az / zz, aw / zw);
    ull_t hp, lp;
    split4(o, hp, lp);
    g_hh[w * 32 + lane] = hp;
    g_hl[w * 32 + lane] = lp;
}

// ---------------- launch ---------------------------------------------------
extern "C" void kernel_launch(void* const* d_in, const int* in_sizes, int n_in,
                              void* d_out, int out_size)
{
    const float* x   = (const float*)d_in[0];
    const int*   src = (const int*)d_in[1];
    const int*   dst = (const int*)d_in[2];
    const float* Wq  = (const float*)d_in[3];
    const float* bq  = (const float*)d_in[4];
    const float* Wk  = (const float*)d_in[5];
    const float* bk  = (const float*)d_in[6];
    const float* Wv  = (const float*)d_in[7];
    const float* bv  = (const float*)d_in[8];
    const float* Wo  = (const float*)d_in[9];
    const float* bo  = (const float*)d_in[10];
    float*       out = (float*)d_out;

    cudaFuncSetAttribute(mma_qkv_kernel,
                         cudaFuncAttributeMaxDynamicSharedMemorySize, MMA_SMEM);
    cudaFuncSetAttribute(mma_out_kernel,
                         cudaFuncAttributeMaxDynamicSharedMemorySize, MMA_SMEM);

    const int mma_blocks  = (NN + 127) / 128;      // 391
    const int zero_blocks = (NN + 255) / 256;      // 196
    const int edge_blocks = (EE + 255) / 256;      // 3125
    const int agg_blocks  = (NN * 32 + 255) / 256; // 6250
    const int px_blocks   = (NN * 32 + 255) / 256; // 6250
    const int pw_blocks   = (4 * 4096 + 255) / 256;

    // bf16 splits first so mma_qkv sits at launch index 3 (profiled slot)
    prep_x_kernel<<<px_blocks, 256>>>(x);
    prep_w_kernel<<<pw_blocks, 256>>>(Wq, Wk, Wv, Wo);
    sniff_kernel<<<1, 512>>>(dst);
    mma_qkv_kernel<<<dim3(mma_blocks, 3), 256, MMA_SMEM>>>(bq, bk, bv);

    // CSR by dst
    zero_cnt_kernel<<<zero_blocks, 256>>>();
    hist_kernel<<<edge_blocks, 256>>>(dst);
    scan_part_kernel<<<SCAN_NB, 256>>>();
    scan_mid_kernel<<<1, 64>>>();
    scan_final_kernel<<<SCAN_NB, 256>>>();
    scatter_kernel<<<edge_blocks, 256>>>(src, dst);

    // edge softmax-aggregate (fp32 gathers, 4-way unroll)
    agg_kernel<<<agg_blocks, 256>>>();

    // output projection
    mma_out_kernel<<<mma_blocks, 256, MMA_SMEM>>>(bo, out);
}

// round 17
// speedup vs baseline: 1.2521x; 1.0690x over previous
#include <cuda_runtime.h>
#include <cuda_bf16.h>
#include <cstdint>

#define NN 50000
#define EE 800000
#define DD 128

typedef unsigned long long ull_t;

// ---------------- scratch (__device__ globals; no runtime allocation) ------
__device__ float g_q[NN * DD];
__device__ float g_k[NN * DD];
__device__ float g_v[NN * DD];
__device__ ull_t g_xh[NN * 32];    // X split hi: [NN][32] ull (128 bf16/row)
__device__ ull_t g_xl[NN * 32];    // X split lo
__device__ ull_t g_hh[NN * 32];    // h (agg out) split hi
__device__ ull_t g_hl[NN * 32];    // h split lo
__device__ ull_t g_wth[4 * 4096];  // W^T hi: [mat][128 n][128 k] bf16
__device__ ull_t g_wtl[4 * 4096];  // W^T lo
__device__ int   g_cnt[NN];        // zero-initialized; scatter restores zeros
__device__ int   g_off[NN + 1];
__device__ int   g_csrc[EE];
__device__ int   g_part[64];
__device__ int   g_pofs[64];
__device__ int   g_stride;         // 1 = int32 indices, 2 = int64 (low word)

// ---------------- bf16 helpers ---------------------------------------------
__device__ __forceinline__ void split4(float4 v, ull_t& hp, ull_t& lp)
{
    __nv_bfloat16 h0 = __float2bfloat16(v.x);
    __nv_bfloat16 h1 = __float2bfloat16(v.y);
    __nv_bfloat16 h2 = __float2bfloat16(v.z);
    __nv_bfloat16 h3 = __float2bfloat16(v.w);
    __nv_bfloat16 l0 = __float2bfloat16(v.x - __bfloat162float(h0));
    __nv_bfloat16 l1 = __float2bfloat16(v.y - __bfloat162float(h1));
    __nv_bfloat16 l2 = __float2bfloat16(v.z - __bfloat162float(h2));
    __nv_bfloat16 l3 = __float2bfloat16(v.w - __bfloat162float(h3));
    hp = (ull_t)__bfloat16_as_ushort(h0)
       | ((ull_t)__bfloat16_as_ushort(h1) << 16)
       | ((ull_t)__bfloat16_as_ushort(h2) << 32)
       | ((ull_t)__bfloat16_as_ushort(h3) << 48);
    lp = (ull_t)__bfloat16_as_ushort(l0)
       | ((ull_t)__bfloat16_as_ushort(l1) << 16)
       | ((ull_t)__bfloat16_as_ushort(l2) << 32)
       | ((ull_t)__bfloat16_as_ushort(l3) << 48);
}

// ---------------- warp-level mma.sync (sm_80+ feature; legal on sm_103) ----
__device__ __forceinline__ void mma_bf16(float* c, const uint32_t* a,
                                         const uint32_t* b)
{
    asm volatile(
        "mma.sync.aligned.m16n8k16.row.col.f32.bf16.bf16.f32 "
        "{%0,%1,%2,%3}, {%4,%5,%6,%7}, {%8,%9}, {%0,%1,%2,%3};"
        : "+f"(c[0]), "+f"(c[1]), "+f"(c[2]), "+f"(c[3])
        : "r"(a[0]), "r"(a[1]), "r"(a[2]), "r"(a[3]), "r"(b[0]), "r"(b[1]));
}

#define SROW 136     // smem Wt row pitch in bf16 (272B)
#define APITCH 5     // smem A chunk row pitch in ull (40B: 32B data + 8B pad)

// ---------------- MMA GEMM core: 128x128 tile, 8 warps ---------------------
__device__ __forceinline__ void mma_core(const ull_t* __restrict__ Ah,
                                         const ull_t* __restrict__ Al,
                                         const ull_t* __restrict__ Wh,
                                         const ull_t* __restrict__ Wl,
                                         const float* __restrict__ bias,
                                         float* __restrict__ C)
{
    extern __shared__ char smem[];
    unsigned short* sh = (unsigned short*)smem;         // Wt hi [128][SROW]
    unsigned short* sl = sh + 128 * SROW;               // Wt lo
    ull_t* sa_h = (ull_t*)(sl + 128 * SROW);            // A hi [128][APITCH]
    ull_t* sa_l = sa_h + 128 * APITCH;                  // A lo

    const int tid  = threadIdx.x;
    const int lane = tid & 31;
    const int w    = tid >> 5;
    const int row0 = blockIdx.x * 128;

    for (int i = tid; i < 4096; i += 256) {
        int r = i >> 5, c = i & 31;
        *(ull_t*)(sh + r * SROW + c * 4) = Wh[i];
        *(ull_t*)(sl + r * SROW + c * 4) = Wl[i];
    }

    const int wr0 = (w & 3) * 32;
    const int wc0 = (w >> 2) * 64;
    const int qr  = lane >> 2;
    const int qm  = lane & 3;

    float acc[2][8][4];
#pragma unroll
    for (int mt = 0; mt < 2; mt++)
#pragma unroll
        for (int nt = 0; nt < 8; nt++)
#pragma unroll
            for (int j = 0; j < 4; j++) acc[mt][nt][j] = 0.f;

#pragma unroll
    for (int c8 = 0; c8 < 8; c8++) {
        const int k0 = c8 * 16;
        __syncthreads();   // prior-iter reads (and W staging) complete
        // stage A chunk: 128 rows x 4 ull x 2 splits; coalesced
#pragma unroll
        for (int it = 0; it < 2; it++) {
            int i  = tid + it * 256;      // 0..511
            int r  = i >> 2;
            int wz = i & 3;
            int gr = row0 + r;
            ull_t vh = 0, vl = 0;
            if (gr < NN) {
                vh = Ah[(size_t)gr * 32 + c8 * 4 + wz];
                vl = Al[(size_t)gr * 32 + c8 * 4 + wz];
            }
            sa_h[r * APITCH + wz] = vh;
            sa_l[r * APITCH + wz] = vl;
        }
        __syncthreads();

        // A fragments
        uint32_t ah[2][4], al[2][4];
#pragma unroll
        for (int mt = 0; mt < 2; mt++) {
            int rl1 = wr0 + mt * 16 + qr;
            int rl2 = rl1 + 8;
            const uint32_t* h1 = (const uint32_t*)(sa_h + rl1 * APITCH);
            const uint32_t* h2 = (const uint32_t*)(sa_h + rl2 * APITCH);
            const uint32_t* l1 = (const uint32_t*)(sa_l + rl1 * APITCH);
            const uint32_t* l2 = (const uint32_t*)(sa_l + rl2 * APITCH);
            ah[mt][0] = h1[qm];
            ah[mt][1] = h2[qm];
            ah[mt][2] = h1[qm + 4];
            ah[mt][3] = h2[qm + 4];
            al[mt][0] = l1[qm];
            al[mt][1] = l2[qm];
            al[mt][2] = l1[qm + 4];
            al[mt][3] = l2[qm + 4];
        }

        // B fragments for all 8 nt
        uint32_t bh[8][2], bl[8][2];
#pragma unroll
        for (int nt = 0; nt < 8; nt++) {
            const int nrow = wc0 + nt * 8 + qr;
            const unsigned short* ph = sh + nrow * SROW + k0 + qm * 2;
            const unsigned short* pl = sl + nrow * SROW + k0 + qm * 2;
            bh[nt][0] = *(const uint32_t*)(ph);
            bh[nt][1] = *(const uint32_t*)(ph + 8);
            bl[nt][0] = *(const uint32_t*)(pl);
            bl[nt][1] = *(const uint32_t*)(pl + 8);
        }

        // term-major MMA issue
#pragma unroll
        for (int nt = 0; nt < 8; nt++)
#pragma unroll
            for (int mt = 0; mt < 2; mt++)
                mma_bf16(acc[mt][nt], ah[mt], bh[nt]);
#pragma unroll
        for (int nt = 0; nt < 8; nt++)
#pragma unroll
            for (int mt = 0; mt < 2; mt++)
                mma_bf16(acc[mt][nt], ah[mt], bl[nt]);
#pragma unroll
        for (int nt = 0; nt < 8; nt++)
#pragma unroll
            for (int mt = 0; mt < 2; mt++)
                mma_bf16(acc[mt][nt], al[mt], bh[nt]);
    }

    // epilogue
#pragma unroll
    for (int nt = 0; nt < 8; nt++) {
        const int cc = wc0 + nt * 8 + qm * 2;
        const float2 bb = *(const float2*)&bias[cc];
#pragma unroll
        for (int mt = 0; mt < 2; mt++) {
            int r1 = row0 + wr0 + mt * 16 + qr;
            int r2 = r1 + 8;
            if (r1 < NN) {
                float2 o = make_float2(acc[mt][nt][0] + bb.x,
                                       acc[mt][nt][1] + bb.y);
                *(float2*)&C[(size_t)r1 * DD + cc] = o;
            }
            if (r2 < NN) {
                float2 o = make_float2(acc[mt][nt][2] + bb.x,
                                       acc[mt][nt][3] + bb.y);
                *(float2*)&C[(size_t)r2 * DD + cc] = o;
            }
        }
    }
}

#define MMA_SMEM (2 * 128 * SROW * 2 + 2 * 128 * APITCH * 8)  // 79872 bytes

__global__ __launch_bounds__(256, 2)
void mma_qkv_kernel(const float* __restrict__ bq, const float* __restrict__ bk,
                    const float* __restrict__ bv)
{
    int sel = blockIdx.y;
    const float* bias = (sel == 0) ? bq : (sel == 1) ? bk : bv;
    float* C          = (sel == 0) ? g_q : (sel == 1) ? g_k : g_v;
    mma_core(g_xh, g_xl, g_wth + sel * 4096, g_wtl + sel * 4096, bias, C);
}

__global__ __launch_bounds__(256, 2)
void mma_out_kernel(const float* __restrict__ bo, float* __restrict__ out)
{
    mma_core(g_hh, g_hl, g_wth + 3 * 4096, g_wtl + 3 * 4096, bo, out);
}

// ---------------- prep kernels ---------------------------------------------
__global__ void prep_x_kernel(const float* __restrict__ x)
{
    int i = blockIdx.x * blockDim.x + threadIdx.x;   // NN*32 ull slots
    if (i < NN * 32) {
        float4 v = *(const float4*)&x[i * 4];
        ull_t hp, lp;
        split4(v, hp, lp);
        g_xh[i] = hp;
        g_xl[i] = lp;
    }
}

__global__ void prep_w_kernel(const float* __restrict__ Wq,
                              const float* __restrict__ Wk,
                              const float* __restrict__ Wv,
                              const float* __restrict__ Wo)
{
    int id = blockIdx.x * blockDim.x + threadIdx.x;
    if (id >= 4 * 4096) return;
    int mat = id >> 12;
    int n   = (id >> 5) & 127;
    int kc  = id & 31;
    const float* W = (mat == 0) ? Wq : (mat == 1) ? Wk : (mat == 2) ? Wv : Wo;
    float4 v = make_float4(W[(kc * 4 + 0) * DD + n], W[(kc * 4 + 1) * DD + n],
                           W[(kc * 4 + 2) * DD + n], W[(kc * 4 + 3) * DD + n]);
    ull_t hp, lp;
    split4(v, hp, lp);
    g_wth[id] = hp;
    g_wtl[id] = lp;
}

// ---------------- dtype sniffer -------------------------------------------
__global__ void sniff_kernel(const int* __restrict__ dstw)
{
    __shared__ int any_nonzero;
    if (threadIdx.x == 0) any_nonzero = 0;
    __syncthreads();
    int v = dstw[2 * threadIdx.x + 1];
    if (v != 0) atomicOr(&any_nonzero, 1);
    __syncthreads();
    if (threadIdx.x == 0) g_stride = any_nonzero ? 1 : 2;
}

// ---------------- CSR build ------------------------------------------------
__global__ void zero_cnt_kernel()
{
    int i = blockIdx.x * blockDim.x + threadIdx.x;
    if (i < NN) g_cnt[i] = 0;
}

__global__ void hist_kernel(const int* __restrict__ dstw)
{
    int e = blockIdx.x * blockDim.x + threadIdx.x;
    if (e < EE) {
        int d = dstw[e * g_stride];
        atomicAdd(&g_cnt[d], 1);
    }
}

#define SCAN_NB 49

__global__ void scan_part_kernel()
{
    __shared__ int warpsum[8];
    int base = blockIdx.x * 1024 + threadIdx.x * 4;
    int s = 0;
#pragma unroll
    for (int j = 0; j < 4; j++) {
        int i = base + j;
        if (i < NN) s += g_cnt[i];
    }
    for (int o = 16; o > 0; o >>= 1) s += __shfl_down_sync(0xffffffffu, s, o);
    if ((threadIdx.x & 31) == 0) warpsum[threadIdx.x >> 5] = s;
    __syncthreads();
    if (threadIdx.x < 8) {
        int v = warpsum[threadIdx.x];
        for (int o = 4; o > 0; o >>= 1) v += __shfl_down_sync(0xffu, v, o);
        if (threadIdx.x == 0) g_part[blockIdx.x] = v;
    }
}

__global__ void scan_mid_kernel()
{
    __shared__ int sh[64];
    int t = threadIdx.x;
    int v = (t < SCAN_NB) ? g_part[t] : 0;
    sh[t] = v;
    __syncthreads();
    for (int o = 1; o < 64; o <<= 1) {
        int u = (t >= o) ? sh[t - o] : 0;
        __syncthreads();
        sh[t] += u;
        __syncthreads();
    }
    if (t < SCAN_NB) g_pofs[t] = (t == 0) ? 0 : sh[t - 1];
}

__global__ void scan_final_kernel()
{
    __shared__ int wpref[8];
    int t = threadIdx.x, lane = t & 31, w = t >> 5;
    int base = blockIdx.x * 1024 + t * 4;
    int c[4];
    int s = 0;
#pragma unroll
    for (int j = 0; j < 4; j++) {
        int i = base + j;
        c[j] = (i < NN) ? g_cnt[i] : 0;
        s += c[j];
    }
    int inc = s;
    for (int o = 1; o < 32; o <<= 1) {
        int u = __shfl_up_sync(0xffffffffu, inc, o);
        if (lane >= o) inc += u;
    }
    if (lane == 31) wpref[w] = inc;
    __syncthreads();
    if (t < 8) {
        int v = wpref[t];
        for (int o = 1; o < 8; o <<= 1) {
            int u = __shfl_up_sync(0xffu, v, o);
            if (t >= o) v += u;
        }
        wpref[t] = v;
    }
    __syncthreads();
    int run = inc - s + (w ? wpref[w - 1] : 0) + g_pofs[blockIdx.x];
#pragma unroll
    for (int j = 0; j < 4; j++) {
        int i = base + j;
        run += c[j];
        if (i < NN) g_off[i + 1] = run;
    }
    if (blockIdx.x == 0 && t == 0) g_off[0] = 0;
}

__global__ void scatter_kernel(const int* __restrict__ srcw,
                               const int* __restrict__ dstw)
{
    int e = blockIdx.x * blockDim.x + threadIdx.x;
    if (e < EE) {
        int st  = g_stride;
        int d   = dstw[e * st];
        int s   = srcw[e * st];
        int pos = atomicSub(&g_cnt[d], 1);
        g_csrc[g_off[d] + pos - 1] = s;
    }
}

// ---------------- aggregation: warp per node, 4-way edge unroll (R13) ------
__global__ void agg_kernel()
{
    int w    = (blockIdx.x * blockDim.x + threadIdx.x) >> 5;
    int lane = threadIdx.x & 31;
    if (w >= NN) return;

    const float4 q4 = *(const float4*)&g_q[w * DD + lane * 4];
    const float qx = q4.x * 0.25f;
    const float qy = q4.y * 0.25f;
    const float qz = q4.z * 0.25f;
    const float qw = q4.w * 0.25f;

    float zx = 0.f, zy = 0.f, zz = 0.f, zw = 0.f;
    float ax = 0.f, ay = 0.f, az = 0.f, aw = 0.f;

    const int beg = g_off[w];
    const int end = g_off[w + 1];

    for (int j0 = beg; j0 < end; j0 += 32) {
        int myS = (j0 + lane < end) ? g_csrc[j0 + lane] : 0;
        int cnt = min(32, end - j0);
        int t = 0;
        for (; t + 4 <= cnt; t += 4) {
            int s0 = __shfl_sync(0xffffffffu, myS, t);
            int s1 = __shfl_sync(0xffffffffu, myS, t + 1);
            int s2 = __shfl_sync(0xffffffffu, myS, t + 2);
            int s3 = __shfl_sync(0xffffffffu, myS, t + 3);
            float4 k0 = *(const float4*)&g_k[(size_t)s0 * DD + lane * 4];
            float4 k1 = *(const float4*)&g_k[(size_t)s1 * DD + lane * 4];
            float4 k2 = *(const float4*)&g_k[(size_t)s2 * DD + lane * 4];
            float4 k3 = *(const float4*)&g_k[(size_t)s3 * DD + lane * 4];
            float4 v0 = *(const float4*)&g_v[(size_t)s0 * DD + lane * 4];
            float4 v1 = *(const float4*)&g_v[(size_t)s1 * DD + lane * 4];
            float4 v2 = *(const float4*)&g_v[(size_t)s2 * DD + lane * 4];
            float4 v3 = *(const float4*)&g_v[(size_t)s3 * DD + lane * 4];
            float m;
            m = __expf(k0.x * qx); zx += m; ax += m * v0.x;
            m = __expf(k0.y * qy); zy += m; ay += m * v0.y;
            m = __expf(k0.z * qz); zz += m; az += m * v0.z;
            m = __expf(k0.w * qw); zw += m; aw += m * v0.w;
            m = __expf(k1.x * qx); zx += m; ax += m * v1.x;
            m = __expf(k1.y * qy); zy += m; ay += m * v1.y;
            m = __expf(k1.z * qz); zz += m; az += m * v1.z;
            m = __expf(k1.w * qw); zw += m; aw += m * v1.w;
            m = __expf(k2.x * qx); zx += m; ax += m * v2.x;
            m = __expf(k2.y * qy); zy += m; ay += m * v2.y;
            m = __expf(k2.z * qz); zz += m; az += m * v2.z;
            m = __expf(k2.w * qw); zw += m; aw += m * v2.w;
            m = __expf(k3.x * qx); zx += m; ax += m * v3.x;
            m = __expf(k3.y * qy); zy += m; ay += m * v3.y;
            m = __expf(k3.z * qz); zz += m; az += m * v3.z;
            m = __expf(k3.w * qw); zw += m; aw += m * v3.w;
        }
        for (; t < cnt; t++) {
            int s = __shfl_sync(0xffffffffu, myS, t);
            const float4 kk = *(const float4*)&g_k[(size_t)s * DD + lane * 4];
            const float4 vv = *(const float4*)&g_v[(size_t)s * DD + lane * 4];
            float m;
            m = __expf(kk.x * qx); zx += m; ax += m * vv.x;
            m = __expf(kk.y * qy); zy += m; ay += m * vv.y;
            m = __expf(kk.z * qz); zz += m; az += m * vv.z;
            m = __expf(kk.w * qw); zw += m; aw += m * vv.w;
        }
    }

    float4 o = make_float4(ax / zx, ay / zy, az / zz, aw / zw);
    ull_t hp, lp;
    split4(o, hp, lp);
    g_hh[w * 32 + lane] = hp;
    g_hl[w * 32 + lane] = lp;
}

// ---------------- launch ---------------------------------------------------
extern "C" void kernel_launch(void* const* d_in, const int* in_sizes, int n_in,
                              void* d_out, int out_size)
{
    const float* x   = (const float*)d_in[0];
    const int*   src = (const int*)d_in[1];
    const int*   dst = (const int*)d_in[2];
    const float* Wq  = (const float*)d_in[3];
    const float* bq  = (const float*)d_in[4];
    const float* Wk  = (const float*)d_in[5];
    const float* bk  = (const float*)d_in[6];
    const float* Wv  = (const float*)d_in[7];
    const float* bv  = (const float*)d_in[8];
    const float* Wo  = (const float*)d_in[9];
    const float* bo  = (const float*)d_in[10];
    float*       out = (float*)d_out;

    // one-time setup (first call is the uncaptured correctness run)
    static cudaStream_t s2 = nullptr;
    static cudaEvent_t  evF = nullptr, evJ = nullptr;
    if (s2 == nullptr) {
        cudaStreamCreate(&s2);
        cudaEventCreateWithFlags(&evF, cudaEventDisableTiming);
        cudaEventCreateWithFlags(&evJ, cudaEventDisableTiming);
        cudaFuncSetAttribute(mma_qkv_kernel,
                             cudaFuncAttributeMaxDynamicSharedMemorySize, MMA_SMEM);
        cudaFuncSetAttribute(mma_out_kernel,
                             cudaFuncAttributeMaxDynamicSharedMemorySize, MMA_SMEM);
    }

    const int mma_blocks  = (NN + 127) / 128;      // 391
    const int zero_blocks = (NN + 255) / 256;      // 196
    const int edge_blocks = (EE + 255) / 256;      // 3125
    const int agg_blocks  = (NN * 32 + 255) / 256; // 6250
    const int px_blocks   = (NN * 32 + 255) / 256; // 6250
    const int pw_blocks   = (4 * 4096 + 255) / 256;

    // fork: CSR chain on side stream, overlapped with prep + qkv GEMMs
    cudaEventRecord(evF, 0);
    cudaStreamWaitEvent(s2, evF, 0);

    sniff_kernel<<<1, 512, 0, s2>>>(dst);
    zero_cnt_kernel<<<zero_blocks, 256, 0, s2>>>();
    hist_kernel<<<edge_blocks, 256, 0, s2>>>(dst);
    scan_part_kernel<<<SCAN_NB, 256, 0, s2>>>();
    scan_mid_kernel<<<1, 64, 0, s2>>>();
    scan_final_kernel<<<SCAN_NB, 256, 0, s2>>>();
    scatter_kernel<<<edge_blocks, 256, 0, s2>>>(src, dst);
    cudaEventRecord(evJ, s2);

    // main stream: bf16 splits + Q/K/V projections (tensor-bound)
    prep_x_kernel<<<px_blocks, 256>>>(x);
    prep_w_kernel<<<pw_blocks, 256>>>(Wq, Wk, Wv, Wo);
    mma_qkv_kernel<<<dim3(mma_blocks, 3), 256, MMA_SMEM>>>(bq, bk, bv);

    // join: agg needs q/k/v + CSR
    cudaStreamWaitEvent(0, evJ, 0);
    agg_kernel<<<agg_blocks, 256>>>();

    // output projection
    mma_out_kernel<<<mma_blocks, 256, MMA_SMEM>>>(bo, out);
}